// round 1
// baseline (speedup 1.0000x reference)
#include <cuda_runtime.h>
#include <cuda_bf16.h>

#define NN 100000
#define EE 1600000
#define DD 128
#define SCAN_B 1024
#define NB ((NN + SCAN_B - 1) / SCAN_B)   // 98

// ---------------- scratch (device globals; no allocation allowed) ----------
__device__ float g_h[NN * DD];
__device__ float g_h2[NN * DD];
__device__ float g_as[NN];
__device__ float g_ad[NN];
__device__ int   g_deg[NN];
__device__ int   g_incl[NN];
__device__ int   g_cursor[NN];
__device__ int   g_rowptr[NN + 1];
__device__ int   g_srcs[EE];
__device__ int   g_bsums[128];

// ---------------- CSR construction -----------------------------------------
__global__ void k_zero() {
    int i = blockIdx.x * blockDim.x + threadIdx.x;
    if (i < NN) { g_deg[i] = 0; g_cursor[i] = 0; }
}

__global__ void k_hist(const int* __restrict__ ei) {
    int e = blockIdx.x * blockDim.x + threadIdx.x;
    if (e < EE) atomicAdd(&g_deg[ei[EE + e]], 1);
}

__global__ void k_scan_block() {
    __shared__ int sh[SCAN_B];
    int i = blockIdx.x * SCAN_B + threadIdx.x;
    int v = (i < NN) ? g_deg[i] : 0;
    sh[threadIdx.x] = v;
    __syncthreads();
    for (int off = 1; off < SCAN_B; off <<= 1) {
        int t = 0;
        if (threadIdx.x >= off) t = sh[threadIdx.x - off];
        __syncthreads();
        if (threadIdx.x >= off) sh[threadIdx.x] += t;
        __syncthreads();
    }
    if (i < NN) g_incl[i] = sh[threadIdx.x];
    if (threadIdx.x == SCAN_B - 1) g_bsums[blockIdx.x] = sh[SCAN_B - 1];
}

__global__ void k_scan_bsums() {
    __shared__ int sh[128];
    int t = threadIdx.x;
    sh[t] = (t < NB) ? g_bsums[t] : 0;
    __syncthreads();
    for (int off = 1; off < 128; off <<= 1) {
        int v = 0;
        if (t >= off) v = sh[t - off];
        __syncthreads();
        if (t >= off) sh[t] += v;
        __syncthreads();
    }
    if (t < NB) g_bsums[t] = sh[t];
}

__global__ void k_scan_fix() {
    int i = blockIdx.x * SCAN_B + threadIdx.x;
    if (i < NN) {
        int off = (blockIdx.x > 0) ? g_bsums[blockIdx.x - 1] : 0;
        g_rowptr[i + 1] = g_incl[i] + off;
    }
    if (i == 0) g_rowptr[0] = 0;
}

__global__ void k_scatter(const int* __restrict__ ei) {
    int e = blockIdx.x * blockDim.x + threadIdx.x;
    if (e >= EE) return;
    int s = ei[e];
    int d = ei[EE + e];
    int pos = g_rowptr[d] + atomicAdd(&g_cursor[d], 1);
    g_srcs[pos] = s;
}

// ---------------- SGEMM: C[n,128] = A[n,128] @ B[128,128] (+bias, +leaky) --
__global__ __launch_bounds__(256) void k_gemm(
    const float* __restrict__ A, const float* __restrict__ B,
    const float* __restrict__ bias, float* __restrict__ C,
    int n, int act)
{
    __shared__ float As[16][132];
    __shared__ float Bs[16][128];
    const int tid = threadIdx.x;
    const int tx = tid & 15;
    const int ty = tid >> 4;
    const int rowBase = blockIdx.x * 128;

    float acc[8][8];
#pragma unroll
    for (int r = 0; r < 8; r++)
#pragma unroll
        for (int c = 0; c < 8; c++) acc[r][c] = 0.f;

    for (int k0 = 0; k0 < 128; k0 += 16) {
        // A tile: 128 rows x 16 cols
#pragma unroll
        for (int i = 0; i < 2; i++) {
            int c = tid + i * 256;       // 0..511 float4 slots
            int r = c >> 2;              // row 0..127
            int kq = c & 3;              // float4 within the 16-col strip
            int gr = rowBase + r;
            float4 v = make_float4(0.f, 0.f, 0.f, 0.f);
            if (gr < n) v = *(const float4*)(A + gr * 128 + k0 + kq * 4);
            As[kq * 4 + 0][r] = v.x;
            As[kq * 4 + 1][r] = v.y;
            As[kq * 4 + 2][r] = v.z;
            As[kq * 4 + 3][r] = v.w;
        }
        // B tile: 16 rows x 128 cols
#pragma unroll
        for (int i = 0; i < 2; i++) {
            int c = tid + i * 256;       // 0..511
            int r = c >> 5;              // 0..15
            int q = c & 31;              // float4 within row
            *(float4*)&Bs[r][q * 4] = *(const float4*)(B + (k0 + r) * 128 + q * 4);
        }
        __syncthreads();
#pragma unroll
        for (int k = 0; k < 16; k++) {
            float a[8], b[8];
            *(float4*)&a[0] = *(const float4*)&As[k][ty * 8];
            *(float4*)&a[4] = *(const float4*)&As[k][ty * 8 + 4];
            *(float4*)&b[0] = *(const float4*)&Bs[k][tx * 8];
            *(float4*)&b[4] = *(const float4*)&Bs[k][tx * 8 + 4];
#pragma unroll
            for (int r = 0; r < 8; r++)
#pragma unroll
                for (int c = 0; c < 8; c++)
                    acc[r][c] += a[r] * b[c];
        }
        __syncthreads();
    }

    float bcol[8];
#pragma unroll
    for (int c = 0; c < 8; c++) bcol[c] = bias ? __ldg(&bias[tx * 8 + c]) : 0.f;

#pragma unroll
    for (int r = 0; r < 8; r++) {
        int gr = rowBase + ty * 8 + r;
        if (gr >= n) continue;
        float o[8];
#pragma unroll
        for (int c = 0; c < 8; c++) {
            float v = acc[r][c] + bcol[c];
            if (act) v = (v > 0.f) ? v : 0.01f * v;
            o[c] = v;
        }
        *(float4*)(C + gr * 128 + tx * 8)     = make_float4(o[0], o[1], o[2], o[3]);
        *(float4*)(C + gr * 128 + tx * 8 + 4) = make_float4(o[4], o[5], o[6], o[7]);
    }
}

// ---------------- per-node attention logits: as = h2.a_src, ad = h2.a_dst --
__global__ __launch_bounds__(256) void k_alphas(
    const float* __restrict__ h2,
    const float* __restrict__ av_src, const float* __restrict__ av_dst)
{
    int w = (blockIdx.x * blockDim.x + threadIdx.x) >> 5;
    int lane = threadIdx.x & 31;
    if (w >= NN) return;
    float4 hv = ((const float4*)(h2 + w * 128))[lane];
    float4 s4 = ((const float4*)av_src)[lane];
    float4 d4 = ((const float4*)av_dst)[lane];
    float s = hv.x * s4.x + hv.y * s4.y + hv.z * s4.z + hv.w * s4.w;
    float d = hv.x * d4.x + hv.y * d4.y + hv.z * d4.z + hv.w * d4.w;
#pragma unroll
    for (int o = 16; o > 0; o >>= 1) {
        s += __shfl_xor_sync(0xffffffffu, s, o);
        d += __shfl_xor_sync(0xffffffffu, d, o);
    }
    if (lane == 0) { g_as[w] = s; g_ad[w] = d; }
}

// ---------------- warp-per-node: softmax aggregate + bias + LN + leaky -----
__global__ __launch_bounds__(256) void k_agg(
    const float* __restrict__ h2,
    const float* __restrict__ bias, const float* __restrict__ gamma,
    const float* __restrict__ beta, float* __restrict__ out)
{
    int v = (blockIdx.x * blockDim.x + threadIdx.x) >> 5;
    int lane = threadIdx.x & 31;
    if (v >= NN) return;

    int beg = g_rowptr[v];
    int end = g_rowptr[v + 1];
    float adv = g_ad[v];

    // pass 1: max
    float mx = -1e30f;
    for (int j = beg + lane; j < end; j += 32) {
        float e = g_as[g_srcs[j]] + adv;
        e = (e > 0.f) ? e : 0.2f * e;
        mx = fmaxf(mx, e);
    }
#pragma unroll
    for (int o = 16; o > 0; o >>= 1)
        mx = fmaxf(mx, __shfl_xor_sync(0xffffffffu, mx, o));

    // pass 2: denom
    float dn = 0.f;
    for (int j = beg + lane; j < end; j += 32) {
        float e = g_as[g_srcs[j]] + adv;
        e = (e > 0.f) ? e : 0.2f * e;
        dn += __expf(e - mx);
    }
#pragma unroll
    for (int o = 16; o > 0; o >>= 1)
        dn += __shfl_xor_sync(0xffffffffu, dn, o);
    float winv = (end > beg) ? 1.f / (dn + 1e-16f) : 0.f;

    // pass 3: weighted accumulate of h2 rows (warp-uniform edge loop)
    float4 acc = make_float4(0.f, 0.f, 0.f, 0.f);
    for (int j = beg; j < end; ++j) {
        int s = g_srcs[j];
        float e = g_as[s] + adv;
        e = (e > 0.f) ? e : 0.2f * e;
        float w = __expf(e - mx) * winv;
        float4 hv = ((const float4*)(h2 + s * 128))[lane];
        acc.x += w * hv.x;
        acc.y += w * hv.y;
        acc.z += w * hv.z;
        acc.w += w * hv.w;
    }

    // + bias
    float4 b4 = ((const float4*)bias)[lane];
    acc.x += b4.x; acc.y += b4.y; acc.z += b4.z; acc.w += b4.w;

    // LayerNorm over 128
    float sum = acc.x + acc.y + acc.z + acc.w;
    float sq  = acc.x * acc.x + acc.y * acc.y + acc.z * acc.z + acc.w * acc.w;
#pragma unroll
    for (int o = 16; o > 0; o >>= 1) {
        sum += __shfl_xor_sync(0xffffffffu, sum, o);
        sq  += __shfl_xor_sync(0xffffffffu, sq, o);
    }
    float mu = sum * (1.f / 128.f);
    float var = sq * (1.f / 128.f) - mu * mu;
    float rstd = rsqrtf(var + 1e-5f);

    float4 g4 = ((const float4*)gamma)[lane];
    float4 be4 = ((const float4*)beta)[lane];
    float4 o4;
    o4.x = (acc.x - mu) * rstd * g4.x + be4.x;
    o4.y = (acc.y - mu) * rstd * g4.y + be4.y;
    o4.z = (acc.z - mu) * rstd * g4.z + be4.z;
    o4.w = (acc.w - mu) * rstd * g4.w + be4.w;
    o4.x = (o4.x > 0.f) ? o4.x : 0.01f * o4.x;
    o4.y = (o4.y > 0.f) ? o4.y : 0.01f * o4.y;
    o4.z = (o4.z > 0.f) ? o4.z : 0.01f * o4.z;
    o4.w = (o4.w > 0.f) ? o4.w : 0.01f * o4.w;
    ((float4*)(out + v * 128))[lane] = o4;
}

// ---------------- launcher --------------------------------------------------
extern "C" void kernel_launch(void* const* d_in, const int* in_sizes, int n_in,
                              void* d_out, int out_size) {
    const float* x       = (const float*)d_in[0];
    const int*   ei      = (const int*)  d_in[1];
    const float* W_in    = (const float*)d_in[2];
    const float* b_in    = (const float*)d_in[3];
    const float* Wl      = (const float*)d_in[4];
    const float* att_src = (const float*)d_in[5];
    const float* att_dst = (const float*)d_in[6];
    const float* bias_l  = (const float*)d_in[7];
    const float* gamma   = (const float*)d_in[8];
    const float* beta    = (const float*)d_in[9];
    float* out = (float*)d_out;

    float *ph = nullptr, *ph2 = nullptr;
    cudaGetSymbolAddress((void**)&ph, g_h);
    cudaGetSymbolAddress((void**)&ph2, g_h2);

    // CSR build (reused by all 4 layers)
    k_zero<<<(NN + 1023) / 1024, 1024>>>();
    k_hist<<<(EE + 255) / 256, 256>>>(ei);
    k_scan_block<<<NB, SCAN_B>>>();
    k_scan_bsums<<<1, 128>>>();
    k_scan_fix<<<NB, SCAN_B>>>();
    k_scatter<<<(EE + 255) / 256, 256>>>(ei);

    const int gemm_blocks = (NN + 127) / 128;
    const int node_warp_blocks = (NN + 7) / 8;   // 8 warps/block

    // input projection: h = leaky(x @ W_in + b_in, 0.01)
    k_gemm<<<gemm_blocks, 256>>>(x, W_in, b_in, ph, NN, 1);

    for (int i = 0; i < 4; i++) {
        k_gemm<<<gemm_blocks, 256>>>(ph, Wl + i * DD * DD, nullptr, ph2, NN, 0);
        k_alphas<<<node_warp_blocks, 256>>>(ph2, att_src + i * DD, att_dst + i * DD);
        float* dst = (i == 3) ? out : ph;
        k_agg<<<node_warp_blocks, 256>>>(ph2, bias_l + i * DD, gamma + i * DD,
                                         beta + i * DD, dst);
    }
}

// round 2
// speedup vs baseline: 1.0095x; 1.0095x over previous
#include <cuda_runtime.h>
#include <cuda_fp16.h>
#include <cuda_bf16.h>

#define NN 100000
#define EE 1600000
#define DD 128
#define SCAN_B 1024
#define NB ((NN + SCAN_B - 1) / SCAN_B)   // 98

typedef unsigned long long u64;

// ---------------- scratch (device globals; no allocation allowed) ----------
__device__ float g_h[NN * DD];
__device__ float g_h2[NN * DD];
__device__ uint2 g_h2h[NN * 32];          // fp16 copy of h2 rows (128 halves = 32 uint2)
__device__ float g_as[NN];
__device__ float g_ad[NN];
__device__ int   g_deg[NN];
__device__ int   g_incl[NN];
__device__ int   g_cursor[NN];
__device__ int   g_rowptr[NN + 1];
__device__ int   g_srcs[EE];
__device__ int   g_bsums[128];

// ---------------- CSR construction -----------------------------------------
__global__ void k_zero() {
    int i = blockIdx.x * blockDim.x + threadIdx.x;
    if (i < NN) { g_deg[i] = 0; g_cursor[i] = 0; }
}

__global__ void k_hist(const int* __restrict__ ei) {
    int e = blockIdx.x * blockDim.x + threadIdx.x;
    if (e < EE) atomicAdd(&g_deg[ei[EE + e]], 1);
}

__global__ void k_scan_block() {
    __shared__ int sh[SCAN_B];
    int i = blockIdx.x * SCAN_B + threadIdx.x;
    int v = (i < NN) ? g_deg[i] : 0;
    sh[threadIdx.x] = v;
    __syncthreads();
    for (int off = 1; off < SCAN_B; off <<= 1) {
        int t = 0;
        if (threadIdx.x >= off) t = sh[threadIdx.x - off];
        __syncthreads();
        if (threadIdx.x >= off) sh[threadIdx.x] += t;
        __syncthreads();
    }
    if (i < NN) g_incl[i] = sh[threadIdx.x];
    if (threadIdx.x == SCAN_B - 1) g_bsums[blockIdx.x] = sh[SCAN_B - 1];
}

__global__ void k_scan_bsums() {
    __shared__ int sh[128];
    int t = threadIdx.x;
    sh[t] = (t < NB) ? g_bsums[t] : 0;
    __syncthreads();
    for (int off = 1; off < 128; off <<= 1) {
        int v = 0;
        if (t >= off) v = sh[t - off];
        __syncthreads();
        if (t >= off) sh[t] += v;
        __syncthreads();
    }
    if (t < NB) g_bsums[t] = sh[t];
}

__global__ void k_scan_fix() {
    int i = blockIdx.x * SCAN_B + threadIdx.x;
    if (i < NN) {
        int off = (blockIdx.x > 0) ? g_bsums[blockIdx.x - 1] : 0;
        g_rowptr[i + 1] = g_incl[i] + off;
    }
    if (i == 0) g_rowptr[0] = 0;
}

__global__ void k_scatter(const int* __restrict__ ei) {
    int e = blockIdx.x * blockDim.x + threadIdx.x;
    if (e >= EE) return;
    int s = ei[e];
    int d = ei[EE + e];
    int pos = g_rowptr[d] + atomicAdd(&g_cursor[d], 1);
    g_srcs[pos] = s;
}

// ---------------- packed fp32x2 FMA (Blackwell FFMA2; ptxas won't auto-fuse) -
__device__ __forceinline__ void ffma2(u64& d, u64 a, u64 b) {
    asm("fma.rn.f32x2 %0, %1, %2, %0;" : "+l"(d) : "l"(a), "l"(b));
}
__device__ __forceinline__ u64 dup2(float a) {
    u64 r;
    asm("mov.b64 %0, {%1, %1};" : "=l"(r) : "f"(a));
    return r;
}
__device__ __forceinline__ void unpack2(float& lo, float& hi, u64 v) {
    asm("mov.b64 {%0, %1}, %2;" : "=f"(lo), "=f"(hi) : "l"(v));
}

// ---------------- SGEMM: C[n,128] = A[n,128] @ B[128,128] (+bias, +leaky) --
__global__ __launch_bounds__(256) void k_gemm(
    const float* __restrict__ A, const float* __restrict__ B,
    const float* __restrict__ bias, float* __restrict__ C,
    int n, int act)
{
    __shared__ float As[16][132];
    __shared__ float Bs[16][128];
    const int tid = threadIdx.x;
    const int tx = tid & 15;
    const int ty = tid >> 4;
    const int rowBase = blockIdx.x * 128;

    u64 acc2[8][4];
#pragma unroll
    for (int r = 0; r < 8; r++)
#pragma unroll
        for (int j = 0; j < 4; j++) acc2[r][j] = 0ull;

    for (int k0 = 0; k0 < 128; k0 += 16) {
        // A tile: 128 rows x 16 cols, transposed into As[k][row]
#pragma unroll
        for (int i = 0; i < 2; i++) {
            int c = tid + i * 256;       // 0..511 float4 slots
            int r = c >> 2;              // row 0..127
            int kq = c & 3;              // float4 within the 16-col strip
            int gr = rowBase + r;
            float4 v = make_float4(0.f, 0.f, 0.f, 0.f);
            if (gr < n) v = *(const float4*)(A + gr * 128 + k0 + kq * 4);
            As[kq * 4 + 0][r] = v.x;
            As[kq * 4 + 1][r] = v.y;
            As[kq * 4 + 2][r] = v.z;
            As[kq * 4 + 3][r] = v.w;
        }
        // B tile: 16 rows x 128 cols
#pragma unroll
        for (int i = 0; i < 2; i++) {
            int c = tid + i * 256;       // 0..511
            int r = c >> 5;              // 0..15
            int q = c & 31;              // float4 within row
            *(float4*)&Bs[r][q * 4] = *(const float4*)(B + (k0 + r) * 128 + q * 4);
        }
        __syncthreads();
#pragma unroll
        for (int k = 0; k < 16; k++) {
            float a[8];
            u64 b2[4];
            *(float4*)&a[0] = *(const float4*)&As[k][ty * 8];
            *(float4*)&a[4] = *(const float4*)&As[k][ty * 8 + 4];
            b2[0] = ((const u64*)&Bs[k][tx * 8])[0];
            b2[1] = ((const u64*)&Bs[k][tx * 8])[1];
            b2[2] = ((const u64*)&Bs[k][tx * 8])[2];
            b2[3] = ((const u64*)&Bs[k][tx * 8])[3];
#pragma unroll
            for (int r = 0; r < 8; r++) {
                u64 a2 = dup2(a[r]);
#pragma unroll
                for (int j = 0; j < 4; j++)
                    ffma2(acc2[r][j], a2, b2[j]);
            }
        }
        __syncthreads();
    }

    float bcol[8];
#pragma unroll
    for (int c = 0; c < 8; c++) bcol[c] = bias ? __ldg(&bias[tx * 8 + c]) : 0.f;

#pragma unroll
    for (int r = 0; r < 8; r++) {
        int gr = rowBase + ty * 8 + r;
        if (gr >= n) continue;
        float o[8];
#pragma unroll
        for (int j = 0; j < 4; j++)
            unpack2(o[2 * j], o[2 * j + 1], acc2[r][j]);
#pragma unroll
        for (int c = 0; c < 8; c++) {
            float v = o[c] + bcol[c];
            if (act) v = (v > 0.f) ? v : 0.01f * v;
            o[c] = v;
        }
        *(float4*)(C + gr * 128 + tx * 8)     = make_float4(o[0], o[1], o[2], o[3]);
        *(float4*)(C + gr * 128 + tx * 8 + 4) = make_float4(o[4], o[5], o[6], o[7]);
    }
}

// ------- per-node attention logits + fp16 row copy --------------------------
__global__ __launch_bounds__(256) void k_alphas(
    const float* __restrict__ h2,
    const float* __restrict__ av_src, const float* __restrict__ av_dst)
{
    int w = (blockIdx.x * blockDim.x + threadIdx.x) >> 5;
    int lane = threadIdx.x & 31;
    if (w >= NN) return;
    float4 hv = ((const float4*)(h2 + w * 128))[lane];
    float4 s4 = ((const float4*)av_src)[lane];
    float4 d4 = ((const float4*)av_dst)[lane];
    float s = hv.x * s4.x + hv.y * s4.y + hv.z * s4.z + hv.w * s4.w;
    float d = hv.x * d4.x + hv.y * d4.y + hv.z * d4.z + hv.w * d4.w;

    // fp16 copy of the row (for the gather in k_agg)
    __half2 p0 = __floats2half2_rn(hv.x, hv.y);
    __half2 p1 = __floats2half2_rn(hv.z, hv.w);
    uint2 packed;
    packed.x = *reinterpret_cast<unsigned*>(&p0);
    packed.y = *reinterpret_cast<unsigned*>(&p1);
    g_h2h[w * 32 + lane] = packed;

#pragma unroll
    for (int o = 16; o > 0; o >>= 1) {
        s += __shfl_xor_sync(0xffffffffu, s, o);
        d += __shfl_xor_sync(0xffffffffu, d, o);
    }
    if (lane == 0) { g_as[w] = s; g_ad[w] = d; }
}

// ------- warp-per-node: online softmax aggregate + bias + LN + leaky --------
__global__ __launch_bounds__(256) void k_agg(
    const float* __restrict__ bias, const float* __restrict__ gamma,
    const float* __restrict__ beta, float* __restrict__ out)
{
    int v = (blockIdx.x * blockDim.x + threadIdx.x) >> 5;
    int lane = threadIdx.x & 31;
    if (v >= NN) return;

    int beg = g_rowptr[v];
    int end = g_rowptr[v + 1];
    float adv = g_ad[v];

    // single online pass: running max + rescaled denom
    float mx = -1e30f, dn = 0.f;
    for (int j = beg + lane; j < end; j += 32) {
        float e = g_as[g_srcs[j]] + adv;
        e = (e > 0.f) ? e : 0.2f * e;
        float mn = fmaxf(mx, e);
        dn = dn * __expf(mx - mn) + __expf(e - mn);
        mx = mn;
    }
#pragma unroll
    for (int o = 16; o > 0; o >>= 1) {
        float mo = __shfl_xor_sync(0xffffffffu, mx, o);
        float do_ = __shfl_xor_sync(0xffffffffu, dn, o);
        float mn = fmaxf(mx, mo);
        dn = dn * __expf(mx - mn) + do_ * __expf(mo - mn);
        mx = mn;
    }
    float winv = (end > beg) ? 1.f / (dn + 1e-16f) : 0.f;

    // weighted accumulate of fp16 rows (warp-uniform edge loop)
    float4 acc = make_float4(0.f, 0.f, 0.f, 0.f);
    for (int j = beg; j < end; ++j) {
        int s = g_srcs[j];
        float e = g_as[s] + adv;
        e = (e > 0.f) ? e : 0.2f * e;
        float w = __expf(e - mx) * winv;
        uint2 hv = g_h2h[s * 32 + lane];
        __half2 h0 = *reinterpret_cast<__half2*>(&hv.x);
        __half2 h1 = *reinterpret_cast<__half2*>(&hv.y);
        float2 f0 = __half22float2(h0);
        float2 f1 = __half22float2(h1);
        acc.x += w * f0.x;
        acc.y += w * f0.y;
        acc.z += w * f1.x;
        acc.w += w * f1.y;
    }

    // + bias
    float4 b4 = ((const float4*)bias)[lane];
    acc.x += b4.x; acc.y += b4.y; acc.z += b4.z; acc.w += b4.w;

    // LayerNorm over 128
    float sum = acc.x + acc.y + acc.z + acc.w;
    float sq  = acc.x * acc.x + acc.y * acc.y + acc.z * acc.z + acc.w * acc.w;
#pragma unroll
    for (int o = 16; o > 0; o >>= 1) {
        sum += __shfl_xor_sync(0xffffffffu, sum, o);
        sq  += __shfl_xor_sync(0xffffffffu, sq, o);
    }
    float mu = sum * (1.f / 128.f);
    float var = sq * (1.f / 128.f) - mu * mu;
    float rstd = rsqrtf(var + 1e-5f);

    float4 g4 = ((const float4*)gamma)[lane];
    float4 be4 = ((const float4*)beta)[lane];
    float4 o4;
    o4.x = (acc.x - mu) * rstd * g4.x + be4.x;
    o4.y = (acc.y - mu) * rstd * g4.y + be4.y;
    o4.z = (acc.z - mu) * rstd * g4.z + be4.z;
    o4.w = (acc.w - mu) * rstd * g4.w + be4.w;
    o4.x = (o4.x > 0.f) ? o4.x : 0.01f * o4.x;
    o4.y = (o4.y > 0.f) ? o4.y : 0.01f * o4.y;
    o4.z = (o4.z > 0.f) ? o4.z : 0.01f * o4.z;
    o4.w = (o4.w > 0.f) ? o4.w : 0.01f * o4.w;
    ((float4*)(out + v * 128))[lane] = o4;
}

// ---------------- launcher --------------------------------------------------
extern "C" void kernel_launch(void* const* d_in, const int* in_sizes, int n_in,
                              void* d_out, int out_size) {
    const float* x       = (const float*)d_in[0];
    const int*   ei      = (const int*)  d_in[1];
    const float* W_in    = (const float*)d_in[2];
    const float* b_in    = (const float*)d_in[3];
    const float* Wl      = (const float*)d_in[4];
    const float* att_src = (const float*)d_in[5];
    const float* att_dst = (const float*)d_in[6];
    const float* bias_l  = (const float*)d_in[7];
    const float* gamma   = (const float*)d_in[8];
    const float* beta    = (const float*)d_in[9];
    float* out = (float*)d_out;

    float *ph = nullptr, *ph2 = nullptr;
    cudaGetSymbolAddress((void**)&ph, g_h);
    cudaGetSymbolAddress((void**)&ph2, g_h2);

    // CSR build (reused by all 4 layers)
    k_zero<<<(NN + 1023) / 1024, 1024>>>();
    k_hist<<<(EE + 255) / 256, 256>>>(ei);
    k_scan_block<<<NB, SCAN_B>>>();
    k_scan_bsums<<<1, 128>>>();
    k_scan_fix<<<NB, SCAN_B>>>();
    k_scatter<<<(EE + 255) / 256, 256>>>(ei);

    const int gemm_blocks = (NN + 127) / 128;
    const int node_warp_blocks = (NN + 7) / 8;   // 8 warps/block

    // input projection: h = leaky(x @ W_in + b_in, 0.01)
    k_gemm<<<gemm_blocks, 256>>>(x, W_in, b_in, ph, NN, 1);

    for (int i = 0; i < 4; i++) {
        k_gemm<<<gemm_blocks, 256>>>(ph, Wl + i * DD * DD, nullptr, ph2, NN, 0);
        k_alphas<<<node_warp_blocks, 256>>>(ph2, att_src + i * DD, att_dst + i * DD);
        float* dst = (i == 3) ? out : ph;
        k_agg<<<node_warp_blocks, 256>>>(bias_l + i * DD, gamma + i * DD,
                                         beta + i * DD, dst);
    }
}